// round 9
// baseline (speedup 1.0000x reference)
#include <cuda_runtime.h>
#include <math.h>

// Problem constants (fixed by reference setup_inputs)
#define B 32
#define C 256
#define SPATIAL 4096
#define NCHUNK 32
#define ROWS_PER_CHUNK 128                  // SPATIAL / NCHUNK
#define X_ELEMS (B * SPATIAL * C)           // 33554432
#define BN_EPS 1e-3f

#define LAG 4
#define TOTAL_ITEMS (2 * B * NCHUNK)        // 2048
#define GRID 296
#define TPB 256

// Device state (reset kernel zeroes the control words every launch)
__device__ float g_psum[B][NCHUNK][C];
__device__ float g_pmax[B][NCHUNK][C];
__device__ float g_gate[B][C];
__device__ unsigned int g_ticket;
__device__ unsigned int g_done[B];
__device__ unsigned int g_flag[B];

__global__ void reset_kernel()
{
    const int t = threadIdx.x;
    if (t == 0) g_ticket = 0u;
    if (t < B) { g_done[t] = 0u; g_flag[t] = 0u; }
}

// item i -> (type: 0=pool, 1=mult, batch b, chunk)
// order: pool(0..LAG) | for g in 0..26: [pool(LAG+1+g), mult(g)] | mult(27..31)
__device__ __forceinline__ void decode_item(int i, int& type, int& b, int& chunk)
{
    const int P0 = 32 * (LAG + 1);          // 160
    const int NG = B - (LAG + 1);           // 27
    if (i < P0) { type = 0; b = i >> 5; chunk = i & 31; return; }
    int j = i - P0;
    if (j < NG * 64) {
        const int g = j >> 6, r = j & 63;
        if (r < 32) { type = 0; b = LAG + 1 + g; chunk = r; }
        else        { type = 1; b = g;           chunk = r - 32; }
        return;
    }
    const int jj = j - NG * 64;
    type = 1; b = NG + (jj >> 5); chunk = jj & 31;
}

__global__ __launch_bounds__(TPB) void fused_kernel(
    const float* __restrict__ in,
    const float* __restrict__ factor,
    const float* __restrict__ W1,
    const float* __restrict__ b1,
    const float* __restrict__ gamma,
    const float* __restrict__ beta,
    const float* __restrict__ bn_mean,
    const float* __restrict__ bn_var,
    const float* __restrict__ Wg,
    const float* __restrict__ bg,
    const float* __restrict__ gumbel,
    float* __restrict__ out,            // (B*SPATIAL*C)
    float* __restrict__ gate_out)       // (B*C) tail of d_out
{
    __shared__ float4 sh_s[TPB];
    __shared__ float4 sh_m[TPB];
    __shared__ float  pool_s[C];
    __shared__ int    sh_ticket;
    __shared__ int    sh_last;

    const int tid = threadIdx.x;
    const float4* in4  = reinterpret_cast<const float4*>(in);
    float4*       out4 = reinterpret_cast<float4*>(out);

    for (;;) {
        if (tid == 0) sh_ticket = (int)atomicAdd(&g_ticket, 1u);
        __syncthreads();
        const int item = sh_ticket;
        __syncthreads();               // protect sh_ticket before next overwrite
        if (item >= TOTAL_ITEMS) break;

        int type, b, chunk;
        decode_item(item, type, b, chunk);

        if (type == 0) {
            // ---------------- pool partial: batch b, chunk ----------------
            const int c4 = (tid & 63) << 2;   // channel base
            const int rg = tid >> 6;          // row group 0..3
            const float4* p = reinterpret_cast<const float4*>(
                in + ((size_t)(b * SPATIAL + chunk * ROWS_PER_CHUNK + rg)) * C + c4);

            float4 s = make_float4(0.f, 0.f, 0.f, 0.f);
            float4 m = make_float4(-INFINITY, -INFINITY, -INFINITY, -INFINITY);
#pragma unroll
            for (int i = 0; i < ROWS_PER_CHUNK / 4; ++i) {
                const float4 v = p[(size_t)i * C];  // stride 4 rows = C float4
                s.x += v.x; s.y += v.y; s.z += v.z; s.w += v.w;
                m.x = fmaxf(m.x, v.x); m.y = fmaxf(m.y, v.y);
                m.z = fmaxf(m.z, v.z); m.w = fmaxf(m.w, v.w);
            }
            sh_s[tid] = s; sh_m[tid] = m;
            __syncthreads();

            if (tid < 64) {
                float4 S = sh_s[tid];
                float4 M = sh_m[tid];
#pragma unroll
                for (int g = 1; g < 4; ++g) {
                    const float4 s2 = sh_s[tid + 64 * g];
                    const float4 m2 = sh_m[tid + 64 * g];
                    S.x += s2.x; S.y += s2.y; S.z += s2.z; S.w += s2.w;
                    M.x = fmaxf(M.x, m2.x); M.y = fmaxf(M.y, m2.y);
                    M.z = fmaxf(M.z, m2.z); M.w = fmaxf(M.w, m2.w);
                }
                *reinterpret_cast<float4*>(&g_psum[b][chunk][tid << 2]) = S;
                *reinterpret_cast<float4*>(&g_pmax[b][chunk][tid << 2]) = M;
                __threadfence();   // writers order their partials before the count
            }
            __syncthreads();
            if (tid == 0)
                sh_last = (atomicAdd(&g_done[b], 1u) == NCHUNK - 1) ? 1 : 0;
            __syncthreads();

            if (sh_last) {
                // -------- gate compute for batch b (whole CTA) --------
                float s1 = 0.f, m1 = -INFINITY;
#pragma unroll
                for (int k = 0; k < NCHUNK; ++k) {
                    s1 += g_psum[b][k][tid];
                    m1 = fmaxf(m1, g_pmax[b][k][tid]);
                }
                const float avg = s1 * (1.0f / (float)SPATIAL);
                const float a0 = factor[0], a1 = factor[1];
                const float fm = fmaxf(a0, a1);
                const float e0 = expf(a0 - fm), e1 = expf(a1 - fm);
                const float inv = 1.0f / (e0 + e1);
                pool_s[tid] = avg * (e0 * inv) + m1 * (e1 * inv);
                __syncthreads();

                float acc = 0.f;
#pragma unroll 8
                for (int k = 0; k < C; ++k)
                    acc = fmaf(pool_s[k], W1[k * C + tid], acc);
                float h = acc + b1[tid];
                h = gamma[tid] * (h - bn_mean[tid]) *
                        (1.0f / sqrtf(bn_var[tid] + BN_EPS)) + beta[tid];
                h = fmaxf(h, 0.f);

                const float l0 = fmaf(h, Wg[tid * 2 + 0], bg[tid * 2 + 0]);
                const float l1 = fmaf(h, Wg[tid * 2 + 1], bg[tid * 2 + 1]);
                const float z0 = l0 + gumbel[(b * C + tid) * 2 + 0];
                const float z1 = l1 + gumbel[(b * C + tid) * 2 + 1];
                const float zm = fmaxf(z0, z1);
                const float q0 = expf(z0 - zm), q1 = expf(z1 - zm);
                const float y1 = q1 / (q0 + q1);
                const float hard1 = (z1 > z0) ? 1.0f : 0.0f; // argmax tie -> 0
                const float w = (hard1 - y1) + y1;           // stop_grad ST

                g_gate[b][tid] = w;
                gate_out[b * C + tid] = w;
                __threadfence();          // each thread fences its own writes
                __syncthreads();
                if (tid == 0) atomicExch(&g_flag[b], 1u);    // release
            }
        } else {
            // ---------------- multiply: batch b, chunk ----------------
            if (tid == 0) {
                while (atomicAdd(&g_flag[b], 0u) == 0u) __nanosleep(200);
                __threadfence();          // acquire
            }
            __syncthreads();

            const float4 gg = *reinterpret_cast<const float4*>(
                &g_gate[b][(tid & 63) << 2]);

            const size_t fb = ((size_t)(b * SPATIAL + chunk * ROWS_PER_CHUNK)) * (C / 4);
#pragma unroll 8
            for (int k = 0; k < 32; ++k) {
                const size_t idx = fb + (size_t)k * 256 + tid;
                float4 v = in4[idx];
                v.x *= gg.x; v.y *= gg.y; v.z *= gg.z; v.w *= gg.w;
                out4[idx] = v;
            }
        }
        __syncthreads();   // shared buffers reused next iteration
    }
}

extern "C" void kernel_launch(void* const* d_in, const int* in_sizes, int n_in,
                              void* d_out, int out_size)
{
    const float* inputs = (const float*)d_in[0];
    const float* factor = (const float*)d_in[1];
    const float* W1     = (const float*)d_in[2];
    const float* b1     = (const float*)d_in[3];
    const float* gamma  = (const float*)d_in[4];
    const float* beta   = (const float*)d_in[5];
    const float* bnm    = (const float*)d_in[6];
    const float* bnv    = (const float*)d_in[7];
    const float* Wg     = (const float*)d_in[8];
    const float* bg     = (const float*)d_in[9];
    const float* gumbel = (const float*)d_in[10];

    float* out = (float*)d_out;
    float* gate_out = out + X_ELEMS;    // (B, C) broadcast gate after x

    reset_kernel<<<1, 128>>>();
    fused_kernel<<<GRID, TPB>>>(inputs, factor, W1, b1, gamma, beta, bnm, bnv,
                                Wg, bg, gumbel, out, gate_out);
}

// round 10
// speedup vs baseline: 1.5849x; 1.5849x over previous
#include <cuda_runtime.h>
#include <math.h>

// Problem constants (fixed by reference setup_inputs)
#define B 32
#define H 64
#define W 64
#define C 256
#define SPATIAL (H * W)                     // 4096
#define NCHUNK 32                           // spatial chunks per batch
#define ROWS_PER_CHUNK (SPATIAL / NCHUNK)   // 128
#define X_ELEMS (B * SPATIAL * C)           // 33554432
#define BN_EPS 1e-3f

// Stage-1 partials (deterministic two-level reduction; no float atomics)
__device__ float g_psum[B][NCHUNK][C];
__device__ float g_pmax[B][NCHUNK][C];

// ---------------------------------------------------------------------------
// Kernel A: per-(batch,chunk) partial sum & max over 128 spatial rows.
// Normal (caching) loads on purpose: the input must stay resident in L2
// so kernel C can re-read it from L2 instead of DRAM.
// ---------------------------------------------------------------------------
__global__ __launch_bounds__(256) void pool_partial_kernel(const float* __restrict__ in)
{
    const int t     = threadIdx.x;
    const int c4    = (t & 63) << 2;     // channel base (multiple of 4)
    const int rg    = t >> 6;            // row group 0..3
    const int chunk = blockIdx.x;
    const int b     = blockIdx.y;

    const float4* p = reinterpret_cast<const float4*>(
        in + ((size_t)(b * SPATIAL + chunk * ROWS_PER_CHUNK + rg)) * C + c4);

    float4 s = make_float4(0.f, 0.f, 0.f, 0.f);
    float4 m = make_float4(-INFINITY, -INFINITY, -INFINITY, -INFINITY);

#pragma unroll
    for (int i = 0; i < ROWS_PER_CHUNK / 4; ++i) {
        const float4 v = p[(size_t)i * C];   // stride 4 rows = C float4
        s.x += v.x; s.y += v.y; s.z += v.z; s.w += v.w;
        m.x = fmaxf(m.x, v.x); m.y = fmaxf(m.y, v.y);
        m.z = fmaxf(m.z, v.z); m.w = fmaxf(m.w, v.w);
    }

    __shared__ float4 sh_s[256];
    __shared__ float4 sh_m[256];
    sh_s[t] = s;
    sh_m[t] = m;
    __syncthreads();

    if (t < 64) {
        float4 S = sh_s[t];
        float4 M = sh_m[t];
#pragma unroll
        for (int g = 1; g < 4; ++g) {
            const float4 s2 = sh_s[t + 64 * g];
            const float4 m2 = sh_m[t + 64 * g];
            S.x += s2.x; S.y += s2.y; S.z += s2.z; S.w += s2.w;
            M.x = fmaxf(M.x, m2.x); M.y = fmaxf(M.y, m2.y);
            M.z = fmaxf(M.z, m2.z); M.w = fmaxf(M.w, m2.w);
        }
        *reinterpret_cast<float4*>(&g_psum[b][chunk][t << 2]) = S;
        *reinterpret_cast<float4*>(&g_pmax[b][chunk][t << 2]) = M;
    }
}

// ---------------------------------------------------------------------------
// Kernel B: one block per batch. Finish pool reduction (fixed order),
// blend avg/max, dense 256x256 + bias, BN, ReLU, per-channel 2-logit
// gumbel-softmax hard gate. Writes gate into the output tail.
// ---------------------------------------------------------------------------
__global__ __launch_bounds__(C) void gate_kernel(
    const float* __restrict__ factor,   // (2,)
    const float* __restrict__ W1,       // (C, C)
    const float* __restrict__ b1,
    const float* __restrict__ gamma,
    const float* __restrict__ beta,
    const float* __restrict__ bn_mean,
    const float* __restrict__ bn_var,
    const float* __restrict__ Wg,       // (C, 2)
    const float* __restrict__ bg,       // (C, 2)
    const float* __restrict__ gumbel,   // (B, C, 2)
    float* __restrict__ gate_out)       // (B, C)
{
    __shared__ float pool_s[C];
    const int b = blockIdx.x;
    const int t = threadIdx.x;

    {
        float s = 0.f;
        float m = -INFINITY;
#pragma unroll
        for (int k = 0; k < NCHUNK; ++k) {
            s += g_psum[b][k][t];
            m = fmaxf(m, g_pmax[b][k][t]);
        }
        const float avg = s * (1.0f / (float)SPATIAL);

        const float a0 = factor[0], a1 = factor[1];
        const float fm = fmaxf(a0, a1);
        const float e0 = expf(a0 - fm), e1 = expf(a1 - fm);
        const float inv = 1.0f / (e0 + e1);
        pool_s[t] = avg * (e0 * inv) + m * (e1 * inv);
    }
    __syncthreads();

    float acc = 0.f;
#pragma unroll 8
    for (int k = 0; k < C; ++k)
        acc = fmaf(pool_s[k], W1[k * C + t], acc);
    float h = acc + b1[t];

    h = gamma[t] * (h - bn_mean[t]) * (1.0f / sqrtf(bn_var[t] + BN_EPS)) + beta[t];
    h = fmaxf(h, 0.f);

    const float l0 = fmaf(h, Wg[t * 2 + 0], bg[t * 2 + 0]);
    const float l1 = fmaf(h, Wg[t * 2 + 1], bg[t * 2 + 1]);
    const float z0 = l0 + gumbel[(b * C + t) * 2 + 0];
    const float z1 = l1 + gumbel[(b * C + t) * 2 + 1];
    const float zm = fmaxf(z0, z1);
    const float q0 = expf(z0 - zm), q1 = expf(z1 - zm);
    const float y1 = q1 / (q0 + q1);
    const float hard1 = (z1 > z0) ? 1.0f : 0.0f;   // jnp.argmax tie -> index 0
    gate_out[b * C + t] = (hard1 - y1) + y1;       // == stop_grad(hard-y)+y
}

// ---------------------------------------------------------------------------
// Kernel C: x = inputs * gate.
//  * reversed block order: re-reads the input most-recently-cached by A first
//    (avoids the LRU streaming pathology; ~94% of input still in L2)
//  * __stcs (evict-first streaming) output stores: the 134MB write stream
//    does NOT evict the cached input from L2
// ---------------------------------------------------------------------------
#define C_F4      (X_ELEMS / 4)          // 8388608 float4
#define C_PER_BLK 1024                   // float4 per block (256 thr * 4)
#define C_BLOCKS  (C_F4 / C_PER_BLK)     // 8192

__global__ __launch_bounds__(256) void apply_gate_kernel(
    const float4* __restrict__ in4,
    const float* __restrict__ gate,      // (B, C)
    float4* __restrict__ out4)
{
    const int blk  = (C_BLOCKS - 1) - blockIdx.x;   // reversed
    const int tid  = threadIdx.x;
    const size_t base = (size_t)blk * C_PER_BLK;

    const size_t i0 = base + 0 * 256 + tid;
    const size_t i1 = base + 1 * 256 + tid;
    const size_t i2 = base + 2 * 256 + tid;
    const size_t i3 = base + 3 * 256 + tid;

    // channel/batch per load (C=256 floats = 64 float4 per channel-row)
    const int c0 = (int)((i0 << 2) & (C - 1));
    const int c1 = (int)((i1 << 2) & (C - 1));
    const int c2 = (int)((i2 << 2) & (C - 1));
    const int c3 = (int)((i3 << 2) & (C - 1));
    const int b0  = (int)(i0 >> 18);   // (i*4) >> 20
    const int b1_ = (int)(i1 >> 18);
    const int b2  = (int)(i2 >> 18);
    const int b3  = (int)(i3 >> 18);

    float4 v0 = in4[i0];
    float4 v1 = in4[i1];
    float4 v2 = in4[i2];
    float4 v3 = in4[i3];

    const float4 g0 = *reinterpret_cast<const float4*>(&gate[b0 * C + c0]);
    const float4 g1 = *reinterpret_cast<const float4*>(&gate[b1_ * C + c1]);
    const float4 g2 = *reinterpret_cast<const float4*>(&gate[b2 * C + c2]);
    const float4 g3 = *reinterpret_cast<const float4*>(&gate[b3 * C + c3]);

    v0.x *= g0.x; v0.y *= g0.y; v0.z *= g0.z; v0.w *= g0.w;
    v1.x *= g1.x; v1.y *= g1.y; v1.z *= g1.z; v1.w *= g1.w;
    v2.x *= g2.x; v2.y *= g2.y; v2.z *= g2.z; v2.w *= g2.w;
    v3.x *= g3.x; v3.y *= g3.y; v3.z *= g3.z; v3.w *= g3.w;

    __stcs(&out4[i0], v0);
    __stcs(&out4[i1], v1);
    __stcs(&out4[i2], v2);
    __stcs(&out4[i3], v3);
}

extern "C" void kernel_launch(void* const* d_in, const int* in_sizes, int n_in,
                              void* d_out, int out_size)
{
    const float* inputs = (const float*)d_in[0];
    const float* factor = (const float*)d_in[1];
    const float* W1     = (const float*)d_in[2];
    const float* b1     = (const float*)d_in[3];
    const float* gamma  = (const float*)d_in[4];
    const float* beta   = (const float*)d_in[5];
    const float* bnm    = (const float*)d_in[6];
    const float* bnv    = (const float*)d_in[7];
    const float* Wg     = (const float*)d_in[8];
    const float* bg     = (const float*)d_in[9];
    const float* gumbel = (const float*)d_in[10];

    float* out = (float*)d_out;
    float* gate_out = out + X_ELEMS;   // (B, C) broadcast gate lives after x

    dim3 gridA(NCHUNK, B);
    pool_partial_kernel<<<gridA, 256>>>(inputs);

    gate_kernel<<<B, C>>>(factor, W1, b1, gamma, beta, bnm, bnv, Wg, bg,
                          gumbel, gate_out);

    apply_gate_kernel<<<C_BLOCKS, 256>>>(
        (const float4*)inputs, gate_out, (float4*)out);
}